// round 1
// baseline (speedup 1.0000x reference)
#include <cuda_runtime.h>

// Problem constants
#define S_LEN  1024
#define HID    1024
#define NH     16
#define DK     64
#define BATCH  4
#define M_TOT  (BATCH * S_LEN)     // 4096
#define QK_SCALE 0.125f            // 64^-0.5
#define NEGV   (-9e15f)

// Scratch (static device globals — allocation-free per harness rules)
__device__ float g_q[BATCH * NH * S_LEN * DK];     // [b][h][s][d]
__device__ float g_k[BATCH * NH * S_LEN * DK];
__device__ float g_v[BATCH * NH * S_LEN * DK];
__device__ float g_att[BATCH * S_LEN * HID];       // [b][s][hid]

// ---------------------------------------------------------------------------
// SGEMM-NT: out[m][n] = sum_k A[m][k] * W[n][k] + bias[n]
// A: [M x K] row-major, W: [N x K] row-major. M=4096, N=1024, K=1024.
// 128x128 tile, BK=8, 256 threads, 8x8 micro-tile.
// qkv != 0: scatter output into [b][h][s][d] layout.
// ---------------------------------------------------------------------------
__global__ __launch_bounds__(256) void sgemm_nt(
    const float* __restrict__ A, const float* __restrict__ W,
    const float* __restrict__ bias, float* __restrict__ out,
    int K, int qkv)
{
    __shared__ float As[8][128];
    __shared__ float Ws[8][128];

    const int bm = blockIdx.y * 128;
    const int bn = blockIdx.x * 128;
    const int tid  = threadIdx.x;
    const int trow = tid >> 4;        // 0..15
    const int tcol = tid & 15;        // 0..15
    const int lrow = tid >> 1;        // 0..127
    const int lk4  = (tid & 1) * 4;   // 0 or 4

    float acc[8][8];
#pragma unroll
    for (int i = 0; i < 8; ++i)
#pragma unroll
        for (int j = 0; j < 8; ++j) acc[i][j] = 0.0f;

    const float* Ap = A + (size_t)(bm + lrow) * K + lk4;
    const float* Wp = W + (size_t)(bn + lrow) * K + lk4;

    for (int kk = 0; kk < K; kk += 8) {
        float4 a4 = *(const float4*)(Ap + kk);
        float4 w4 = *(const float4*)(Wp + kk);
        __syncthreads();   // previous compute done before overwrite
        As[lk4 + 0][lrow] = a4.x; As[lk4 + 1][lrow] = a4.y;
        As[lk4 + 2][lrow] = a4.z; As[lk4 + 3][lrow] = a4.w;
        Ws[lk4 + 0][lrow] = w4.x; Ws[lk4 + 1][lrow] = w4.y;
        Ws[lk4 + 2][lrow] = w4.z; Ws[lk4 + 3][lrow] = w4.w;
        __syncthreads();
#pragma unroll
        for (int k = 0; k < 8; ++k) {
            float ra[8], rw[8];
            *(float4*)&ra[0] = *(const float4*)&As[k][trow * 8];
            *(float4*)&ra[4] = *(const float4*)&As[k][trow * 8 + 4];
            *(float4*)&rw[0] = *(const float4*)&Ws[k][tcol * 8];
            *(float4*)&rw[4] = *(const float4*)&Ws[k][tcol * 8 + 4];
#pragma unroll
            for (int i = 0; i < 8; ++i)
#pragma unroll
                for (int j = 0; j < 8; ++j)
                    acc[i][j] = fmaf(ra[i], rw[j], acc[i][j]);
        }
    }

    float bv[8];
#pragma unroll
    for (int j = 0; j < 8; ++j) bv[j] = bias[bn + tcol * 8 + j];

#pragma unroll
    for (int i = 0; i < 8; ++i) {
        const int m = bm + trow * 8 + i;
#pragma unroll
        for (int j = 0; j < 8; ++j) {
            const int n = bn + tcol * 8 + j;
            const float c = acc[i][j] + bv[j];
            if (qkv) {
                const int b = m >> 10, s = m & 1023;
                const int h = n >> 6,  d = n & 63;
                out[(((size_t)(b * NH + h) * S_LEN) + s) * DK + d] = c;
            } else {
                out[(size_t)m * HID + n] = c;
            }
        }
    }
}

// ---------------------------------------------------------------------------
// Flash-style attention with bias + zero-mask.
// Block: (b, h, 64-query tile). 256 threads: ty = tid/8 (32 q-pairs),
// tx = tid%8. Score micro-tile 2(q) x 4(k); PV micro-tile 2(q) x 8(d).
// K-tiles of 32. Online softmax.
// ---------------------------------------------------------------------------
__global__ __launch_bounds__(256) void attn_kernel(
    const float* __restrict__ Qg, const float* __restrict__ Kg,
    const float* __restrict__ Vg, const float* __restrict__ Bias,
    float* __restrict__ O)
{
    __shared__ float Qs[64][64];   // [d][q], pre-scaled
    __shared__ float Ks[64][32];   // [d][k]
    __shared__ float Vs[32][64];   // [k][d]
    __shared__ float Ps[32][64];   // [k][q]

    const int q0 = blockIdx.x * 64;
    const int h  = blockIdx.y;
    const int b  = blockIdx.z;
    const int bh = b * NH + h;

    const float* qp = Qg + (size_t)bh * S_LEN * DK;
    const float* kp = Kg + (size_t)bh * S_LEN * DK;
    const float* vp = Vg + (size_t)bh * S_LEN * DK;
    const float* bp = Bias + (size_t)bh * S_LEN * S_LEN;

    const int tid = threadIdx.x;
    const int tx = tid & 7;     // k/d group
    const int ty = tid >> 3;    // q group (0..31)

    // Load + transpose + scale Q tile: 64x64 = 1024 float4s
#pragma unroll
    for (int t = 0; t < 4; ++t) {
        const int id = t * 256 + tid;
        const int qq = id >> 4, d4 = (id & 15) * 4;
        float4 v4 = *(const float4*)&qp[(size_t)(q0 + qq) * DK + d4];
        Qs[d4 + 0][qq] = v4.x * QK_SCALE;
        Qs[d4 + 1][qq] = v4.y * QK_SCALE;
        Qs[d4 + 2][qq] = v4.z * QK_SCALE;
        Qs[d4 + 3][qq] = v4.w * QK_SCALE;
    }

    float mrow[2] = { -1e30f, -1e30f };
    float lrow[2] = { 0.0f, 0.0f };
    float acc_o[2][8];
#pragma unroll
    for (int i = 0; i < 2; ++i)
#pragma unroll
        for (int j = 0; j < 8; ++j) acc_o[i][j] = 0.0f;

    for (int kk = 0; kk < S_LEN; kk += 32) {
        __syncthreads();   // previous PV reads of Vs/Ps finished
        // Load K (transposed) and V tiles: 32x64 each = 512 float4s
#pragma unroll
        for (int t = 0; t < 2; ++t) {
            const int id = t * 256 + tid;
            const int kr = id >> 4, d4 = (id & 15) * 4;
            float4 k4 = *(const float4*)&kp[(size_t)(kk + kr) * DK + d4];
            Ks[d4 + 0][kr] = k4.x; Ks[d4 + 1][kr] = k4.y;
            Ks[d4 + 2][kr] = k4.z; Ks[d4 + 3][kr] = k4.w;
            float4 v4 = *(const float4*)&vp[(size_t)(kk + kr) * DK + d4];
            *(float4*)&Vs[kr][d4] = v4;
        }
        __syncthreads();

        // Scores: s[2][4] = Q_tile @ K_tile^T
        float s[2][4];
#pragma unroll
        for (int i = 0; i < 2; ++i)
#pragma unroll
            for (int j = 0; j < 4; ++j) s[i][j] = 0.0f;
#pragma unroll 8
        for (int d = 0; d < 64; ++d) {
            const float rq0 = Qs[d][ty * 2 + 0];
            const float rq1 = Qs[d][ty * 2 + 1];
            float rk[4];
            *(float4*)&rk[0] = *(const float4*)&Ks[d][tx * 4];
#pragma unroll
            for (int j = 0; j < 4; ++j) {
                s[0][j] = fmaf(rq0, rk[j], s[0][j]);
                s[1][j] = fmaf(rq1, rk[j], s[1][j]);
            }
        }

        // Mask, bias, online softmax
#pragma unroll
        for (int i = 0; i < 2; ++i) {
            const int qrow = q0 + ty * 2 + i;
            float4 b4 = *(const float4*)&bp[(size_t)qrow * S_LEN + kk + tx * 4];
            float sv[4];
            sv[0] = (s[i][0] == 0.0f ? NEGV : s[i][0]) + b4.x;
            sv[1] = (s[i][1] == 0.0f ? NEGV : s[i][1]) + b4.y;
            sv[2] = (s[i][2] == 0.0f ? NEGV : s[i][2]) + b4.z;
            sv[3] = (s[i][3] == 0.0f ? NEGV : s[i][3]) + b4.w;

            float tmax = fmaxf(fmaxf(sv[0], sv[1]), fmaxf(sv[2], sv[3]));
#pragma unroll
            for (int off = 4; off > 0; off >>= 1)
                tmax = fmaxf(tmax, __shfl_xor_sync(0xffffffffu, tmax, off));

            const float mn = fmaxf(mrow[i], tmax);
            const float corr = __expf(mrow[i] - mn);
            float psum = 0.0f;
#pragma unroll
            for (int j = 0; j < 4; ++j) {
                const float p = __expf(sv[j] - mn);
                Ps[tx * 4 + j][ty * 2 + i] = p;
                psum += p;
            }
#pragma unroll
            for (int off = 4; off > 0; off >>= 1)
                psum += __shfl_xor_sync(0xffffffffu, psum, off);

            lrow[i] = lrow[i] * corr + psum;
            mrow[i] = mn;
#pragma unroll
            for (int j = 0; j < 8; ++j) acc_o[i][j] *= corr;
        }
        __syncthreads();

        // PV: acc_o += P_tile @ V_tile
#pragma unroll 8
        for (int k = 0; k < 32; ++k) {
            const float rp0 = Ps[k][ty * 2 + 0];
            const float rp1 = Ps[k][ty * 2 + 1];
            float rv[8];
            *(float4*)&rv[0] = *(const float4*)&Vs[k][tx * 8];
            *(float4*)&rv[4] = *(const float4*)&Vs[k][tx * 8 + 4];
#pragma unroll
            for (int j = 0; j < 8; ++j) {
                acc_o[0][j] = fmaf(rp0, rv[j], acc_o[0][j]);
                acc_o[1][j] = fmaf(rp1, rv[j], acc_o[1][j]);
            }
        }
    }

    // Write O in [b][s][hid] layout
#pragma unroll
    for (int i = 0; i < 2; ++i) {
        const float inv_l = 1.0f / lrow[i];
        const int qrow = q0 + ty * 2 + i;
#pragma unroll
        for (int j = 0; j < 8; ++j) {
            O[((size_t)(b * S_LEN + qrow)) * HID + h * DK + tx * 8 + j] =
                acc_o[i][j] * inv_l;
        }
    }
}

// ---------------------------------------------------------------------------
extern "C" void kernel_launch(void* const* d_in, const int* in_sizes, int n_in,
                              void* d_out, int out_size)
{
    const float* batch = (const float*)d_in[0];
    const float* bias  = (const float*)d_in[1];
    const float* Wq = (const float*)d_in[2];
    const float* bq = (const float*)d_in[3];
    const float* Wk = (const float*)d_in[4];
    const float* bk = (const float*)d_in[5];
    const float* Wv = (const float*)d_in[6];
    const float* bv = (const float*)d_in[7];
    const float* Wo = (const float*)d_in[8];
    const float* bo = (const float*)d_in[9];
    float* out = (float*)d_out;

    float *qptr, *kptr, *vptr, *aptr;
    cudaGetSymbolAddress((void**)&qptr, g_q);
    cudaGetSymbolAddress((void**)&kptr, g_k);
    cudaGetSymbolAddress((void**)&vptr, g_v);
    cudaGetSymbolAddress((void**)&aptr, g_att);

    dim3 ggrid(HID / 128, M_TOT / 128);   // (8, 32)
    sgemm_nt<<<ggrid, 256>>>(batch, Wq, bq, qptr, HID, 1);
    sgemm_nt<<<ggrid, 256>>>(batch, Wk, bk, kptr, HID, 1);
    sgemm_nt<<<ggrid, 256>>>(batch, Wv, bv, vptr, HID, 1);

    dim3 agrid(S_LEN / 64, NH, BATCH);    // (16, 16, 4)
    attn_kernel<<<agrid, 256>>>(qptr, kptr, vptr, bias, aptr);

    sgemm_nt<<<ggrid, 256>>>(aptr, Wo, bo, out, HID, 0);
}

// round 3
// speedup vs baseline: 2.2835x; 2.2835x over previous
#include <cuda_runtime.h>
#include <cstdint>

// Problem constants
#define S_LEN  1024
#define HID    1024
#define NH     16
#define DK     64
#define BATCH  4
#define M_TOT  (BATCH * S_LEN)     // 4096
#define QK_SCALE 0.125f            // 64^-0.5
#define NEGV   (-9e15f)

// Scratch (static device globals — allocation-free per harness rules)
__device__ float g_q[BATCH * NH * S_LEN * DK];     // [b][h][s][d]
__device__ float g_k[BATCH * NH * S_LEN * DK];
__device__ float g_v[BATCH * NH * S_LEN * DK];
__device__ float g_att[BATCH * S_LEN * HID];       // [b][s][hid]

__device__ __forceinline__ uint32_t f2tf32(float f) {
    uint32_t r;
    asm("cvt.rna.tf32.f32 %0, %1;" : "=r"(r) : "f"(f));
    return r;
}

__device__ __forceinline__ void mma_tf32(float c[4], const uint32_t a[4],
                                         const uint32_t b[2]) {
    asm volatile(
        "mma.sync.aligned.m16n8k8.row.col.f32.tf32.tf32.f32 "
        "{%0,%1,%2,%3}, {%4,%5,%6,%7}, {%8,%9}, {%0,%1,%2,%3};"
        : "+f"(c[0]), "+f"(c[1]), "+f"(c[2]), "+f"(c[3])
        : "r"(a[0]), "r"(a[1]), "r"(a[2]), "r"(a[3]),
          "r"(b[0]), "r"(b[1]));
}

// ---------------------------------------------------------------------------
// TF32 mma.sync GEMM-NT: out[m][n] = sum_k A[m][k] * W[n][k] + bias[n]
// M=4096, N=1024, K=1024. CTA tile 128x128, BK=32, 256 thr (8 warps),
// warp tile 32x64 (2x8 mma tiles of 16x8), double-buffered smem.
// qkv != 0: scatter output into [b][h][s][d].
// ---------------------------------------------------------------------------
#define PAD   36                       // 32 cols + 4 pad (floats)
#define TILEF (128 * PAD)              // floats per tile buffer
#define GEMM_SMEM_BYTES (4 * TILEF * 4)  // A0,W0,A1,W1 = 73728 B

__global__ __launch_bounds__(256) void gemm_mma(
    const float* __restrict__ A, const float* __restrict__ W,
    const float* __restrict__ bias, float* __restrict__ out, int qkv)
{
    extern __shared__ float sm[];
    float* sA[2] = { sm,             sm + 2 * TILEF };
    float* sW[2] = { sm + TILEF,     sm + 3 * TILEF };

    const int tid = threadIdx.x;
    const int wid = tid >> 5, lid = tid & 31;
    const int bn = blockIdx.x * 128;
    const int bm = blockIdx.y * 128;

    const int wm = wid >> 1;           // 0..3 (m strip of 32)
    const int wn = wid & 1;            // 0..1 (n strip of 64)
    const int g  = lid >> 2;           // 0..7
    const int tg = lid & 3;            // 0..3

    float c[2][8][4];
#pragma unroll
    for (int mi = 0; mi < 2; ++mi)
#pragma unroll
        for (int ni = 0; ni < 8; ++ni)
#pragma unroll
            for (int k = 0; k < 4; ++k) c[mi][ni][k] = 0.0f;

    // global load map: idx = tid + t*256 in [0,1024): row = idx>>3, c4 = idx&7
    float4 ra[4], rw[4];
#define LOAD_REGS(kk)                                                         \
    do {                                                                      \
        _Pragma("unroll")                                                     \
        for (int t = 0; t < 4; ++t) {                                         \
            const int idx = tid + t * 256;                                    \
            const int row = idx >> 3, c4 = idx & 7;                           \
            ra[t] = *(const float4*)(A + (size_t)(bm + row) * 1024 + (kk) + c4 * 4); \
            rw[t] = *(const float4*)(W + (size_t)(bn + row) * 1024 + (kk) + c4 * 4); \
        }                                                                     \
    } while (0)

#define STORE_SMEM(buf)                                                       \
    do {                                                                      \
        _Pragma("unroll")                                                     \
        for (int t = 0; t < 4; ++t) {                                         \
            const int idx = tid + t * 256;                                    \
            const int row = idx >> 3, c4 = idx & 7;                           \
            float* pa = sA[buf] + row * PAD + c4 * 4;                         \
            float* pw = sW[buf] + row * PAD + c4 * 4;                         \
            pa[0] = __uint_as_float(f2tf32(ra[t].x));                         \
            pa[1] = __uint_as_float(f2tf32(ra[t].y));                         \
            pa[2] = __uint_as_float(f2tf32(ra[t].z));                         \
            pa[3] = __uint_as_float(f2tf32(ra[t].w));                         \
            pw[0] = __uint_as_float(f2tf32(rw[t].x));                         \
            pw[1] = __uint_as_float(f2tf32(rw[t].y));                         \
            pw[2] = __uint_as_float(f2tf32(rw[t].z));                         \
            pw[3] = __uint_as_float(f2tf32(rw[t].w));                         \
        }                                                                     \
    } while (0)

    LOAD_REGS(0);
    STORE_SMEM(0);
    __syncthreads();

    for (int i = 0; i < 32; ++i) {
        const int cur = i & 1;
        if (i + 1 < 32) LOAD_REGS((i + 1) * 32);

        const float* As = sA[cur];
        const float* Ws = sW[cur];
#pragma unroll
        for (int ks = 0; ks < 4; ++ks) {
            const int kb = ks * 8;
            uint32_t af[2][4];
#pragma unroll
            for (int mi = 0; mi < 2; ++mi) {
                const int r0 = (wm * 32 + mi * 16 + g) * PAD + kb + tg;
                af[mi][0] = __float_as_uint(As[r0]);
                af[mi][1] = __float_as_uint(As[r0 + 8 * PAD]);
                af[mi][2] = __float_as_uint(As[r0 + 4]);
                af[mi][3] = __float_as_uint(As[r0 + 8 * PAD + 4]);
            }
            uint32_t bf[8][2];
#pragma unroll
            for (int ni = 0; ni < 8; ++ni) {
                const int r0 = (wn * 64 + ni * 8 + g) * PAD + kb + tg;
                bf[ni][0] = __float_as_uint(Ws[r0]);
                bf[ni][1] = __float_as_uint(Ws[r0 + 4]);
            }
#pragma unroll
            for (int mi = 0; mi < 2; ++mi)
#pragma unroll
                for (int ni = 0; ni < 8; ++ni)
                    mma_tf32(c[mi][ni], af[mi], bf[ni]);
        }

        if (i + 1 < 32) {
            __syncthreads();
            STORE_SMEM((i + 1) & 1);
            __syncthreads();
        }
    }

    // Epilogue: c[mi][ni][{0,1}] -> (row, col..col+1), [{2,3}] -> row+8
#pragma unroll
    for (int mi = 0; mi < 2; ++mi) {
        const int rowa = bm + wm * 32 + mi * 16 + g;
        const int rowb = rowa + 8;
#pragma unroll
        for (int ni = 0; ni < 8; ++ni) {
            const int col = bn + wn * 64 + ni * 8 + tg * 2;
            const float b0 = bias[col], b1 = bias[col + 1];
            float2 v0 = make_float2(c[mi][ni][0] + b0, c[mi][ni][1] + b1);
            float2 v1 = make_float2(c[mi][ni][2] + b0, c[mi][ni][3] + b1);
            if (qkv) {
                const int h = col >> 6, d = col & 63;
                const int ba = rowa >> 10, sa = rowa & 1023;
                const int bb = rowb >> 10, sb2 = rowb & 1023;
                *(float2*)(out + (((size_t)(ba * NH + h) * S_LEN + sa) * DK + d)) = v0;
                *(float2*)(out + (((size_t)(bb * NH + h) * S_LEN + sb2) * DK + d)) = v1;
            } else {
                *(float2*)(out + (size_t)rowa * HID + col) = v0;
                *(float2*)(out + (size_t)rowb * HID + col) = v1;
            }
        }
    }
}

// ---------------------------------------------------------------------------
// Flash-style attention with bias + zero-mask (SIMT fp32).
// ---------------------------------------------------------------------------
__global__ __launch_bounds__(256) void attn_kernel(
    const float* __restrict__ Qg, const float* __restrict__ Kg,
    const float* __restrict__ Vg, const float* __restrict__ Bias,
    float* __restrict__ O)
{
    __shared__ float Qs[64][64];   // [d][q], pre-scaled
    __shared__ float Ks[64][32];   // [d][k]
    __shared__ float Vs[32][64];   // [k][d]
    __shared__ float Ps[32][64];   // [k][q]

    const int q0 = blockIdx.x * 64;
    const int h  = blockIdx.y;
    const int b  = blockIdx.z;
    const int bh = b * NH + h;

    const float* qp = Qg + (size_t)bh * S_LEN * DK;
    const float* kp = Kg + (size_t)bh * S_LEN * DK;
    const float* vp = Vg + (size_t)bh * S_LEN * DK;
    const float* bp = Bias + (size_t)bh * S_LEN * S_LEN;

    const int tid = threadIdx.x;
    const int tx = tid & 7;
    const int ty = tid >> 3;

#pragma unroll
    for (int t = 0; t < 4; ++t) {
        const int id = t * 256 + tid;
        const int qq = id >> 4, d4 = (id & 15) * 4;
        float4 v4 = *(const float4*)&qp[(size_t)(q0 + qq) * DK + d4];
        Qs[d4 + 0][qq] = v4.x * QK_SCALE;
        Qs[d4 + 1][qq] = v4.y * QK_SCALE;
        Qs[d4 + 2][qq] = v4.z * QK_SCALE;
        Qs[d4 + 3][qq] = v4.w * QK_SCALE;
    }

    float mrow[2] = { -1e30f, -1e30f };
    float lrow[2] = { 0.0f, 0.0f };
    float acc_o[2][8];
#pragma unroll
    for (int i = 0; i < 2; ++i)
#pragma unroll
        for (int j = 0; j < 8; ++j) acc_o[i][j] = 0.0f;

    for (int kk = 0; kk < S_LEN; kk += 32) {
        __syncthreads();
#pragma unroll
        for (int t = 0; t < 2; ++t) {
            const int id = t * 256 + tid;
            const int kr = id >> 4, d4 = (id & 15) * 4;
            float4 k4 = *(const float4*)&kp[(size_t)(kk + kr) * DK + d4];
            Ks[d4 + 0][kr] = k4.x; Ks[d4 + 1][kr] = k4.y;
            Ks[d4 + 2][kr] = k4.z; Ks[d4 + 3][kr] = k4.w;
            float4 v4 = *(const float4*)&vp[(size_t)(kk + kr) * DK + d4];
            *(float4*)&Vs[kr][d4] = v4;
        }
        __syncthreads();

        float s[2][4];
#pragma unroll
        for (int i = 0; i < 2; ++i)
#pragma unroll
            for (int j = 0; j < 4; ++j) s[i][j] = 0.0f;
#pragma unroll 8
        for (int d = 0; d < 64; ++d) {
            const float rq0 = Qs[d][ty * 2 + 0];
            const float rq1 = Qs[d][ty * 2 + 1];
            float rk[4];
            *(float4*)&rk[0] = *(const float4*)&Ks[d][tx * 4];
#pragma unroll
            for (int j = 0; j < 4; ++j) {
                s[0][j] = fmaf(rq0, rk[j], s[0][j]);
                s[1][j] = fmaf(rq1, rk[j], s[1][j]);
            }
        }

#pragma unroll
        for (int i = 0; i < 2; ++i) {
            const int qrow = q0 + ty * 2 + i;
            float4 b4 = *(const float4*)&bp[(size_t)qrow * S_LEN + kk + tx * 4];
            float sv[4];
            sv[0] = (s[i][0] == 0.0f ? NEGV : s[i][0]) + b4.x;
            sv[1] = (s[i][1] == 0.0f ? NEGV : s[i][1]) + b4.y;
            sv[2] = (s[i][2] == 0.0f ? NEGV : s[i][2]) + b4.z;
            sv[3] = (s[i][3] == 0.0f ? NEGV : s[i][3]) + b4.w;

            float tmax = fmaxf(fmaxf(sv[0], sv[1]), fmaxf(sv[2], sv[3]));
#pragma unroll
            for (int off = 4; off > 0; off >>= 1)
                tmax = fmaxf(tmax, __shfl_xor_sync(0xffffffffu, tmax, off));

            const float mn = fmaxf(mrow[i], tmax);
            const float corr = __expf(mrow[i] - mn);
            float psum = 0.0f;
#pragma unroll
            for (int j = 0; j < 4; ++j) {
                const float p = __expf(sv[j] - mn);
                Ps[tx * 4 + j][ty * 2 + i] = p;
                psum += p;
            }
#pragma unroll
            for (int off = 4; off > 0; off >>= 1)
                psum += __shfl_xor_sync(0xffffffffu, psum, off);

            lrow[i] = lrow[i] * corr + psum;
            mrow[i] = mn;
#pragma unroll
            for (int j = 0; j < 8; ++j) acc_o[i][j] *= corr;
        }
        __syncthreads();

#pragma unroll 8
        for (int k = 0; k < 32; ++k) {
            const float rp0 = Ps[k][ty * 2 + 0];
            const float rp1 = Ps[k][ty * 2 + 1];
            float rv[8];
            *(float4*)&rv[0] = *(const float4*)&Vs[k][tx * 8];
            *(float4*)&rv[4] = *(const float4*)&Vs[k][tx * 8 + 4];
#pragma unroll
            for (int j = 0; j < 8; ++j) {
                acc_o[0][j] = fmaf(rp0, rv[j], acc_o[0][j]);
                acc_o[1][j] = fmaf(rp1, rv[j], acc_o[1][j]);
            }
        }
    }

#pragma unroll
    for (int i = 0; i < 2; ++i) {
        const float inv_l = 1.0f / lrow[i];
        const int qrow = q0 + ty * 2 + i;
#pragma unroll
        for (int j = 0; j < 8; ++j) {
            O[((size_t)(b * S_LEN + qrow)) * HID + h * DK + tx * 8 + j] =
                acc_o[i][j] * inv_l;
        }
    }
}

// ---------------------------------------------------------------------------
extern "C" void kernel_launch(void* const* d_in, const int* in_sizes, int n_in,
                              void* d_out, int out_size)
{
    const float* batch = (const float*)d_in[0];
    const float* bias  = (const float*)d_in[1];
    const float* Wq = (const float*)d_in[2];
    const float* bq = (const float*)d_in[3];
    const float* Wk = (const float*)d_in[4];
    const float* bk = (const float*)d_in[5];
    const float* Wv = (const float*)d_in[6];
    const float* bv = (const float*)d_in[7];
    const float* Wo = (const float*)d_in[8];
    const float* bo = (const float*)d_in[9];
    float* out = (float*)d_out;

    float *qptr, *kptr, *vptr, *aptr;
    cudaGetSymbolAddress((void**)&qptr, g_q);
    cudaGetSymbolAddress((void**)&kptr, g_k);
    cudaGetSymbolAddress((void**)&vptr, g_v);
    cudaGetSymbolAddress((void**)&aptr, g_att);

    static int smem_set = 0;
    if (!smem_set) {
        cudaFuncSetAttribute(gemm_mma,
                             cudaFuncAttributeMaxDynamicSharedMemorySize,
                             GEMM_SMEM_BYTES);
        smem_set = 1;
    }

    dim3 ggrid(HID / 128, M_TOT / 128);   // (8, 32)
    gemm_mma<<<ggrid, 256, GEMM_SMEM_BYTES>>>(batch, Wq, bq, qptr, 1);
    gemm_mma<<<ggrid, 256, GEMM_SMEM_BYTES>>>(batch, Wk, bk, kptr, 1);
    gemm_mma<<<ggrid, 256, GEMM_SMEM_BYTES>>>(batch, Wv, bv, vptr, 1);

    dim3 agrid(S_LEN / 64, NH, BATCH);    // (16, 16, 4)
    attn_kernel<<<agrid, 256>>>(qptr, kptr, vptr, bias, aptr);

    gemm_mma<<<ggrid, 256, GEMM_SMEM_BYTES>>>(aptr, Wo, bo, out, 0);
}

// round 4
// speedup vs baseline: 5.0444x; 2.2091x over previous
#include <cuda_runtime.h>
#include <cstdint>

// Problem constants
#define S_LEN  1024
#define HID    1024
#define NH     16
#define DK     64
#define BATCH  4
#define M_TOT  (BATCH * S_LEN)     // 4096
#define QK_SCALE 0.125f            // 64^-0.5
#define NEGV   (-9e15f)

// Scratch (static device globals — allocation-free per harness rules)
__device__ float g_q[BATCH * NH * S_LEN * DK];     // [b][h][s][d]
__device__ float g_k[BATCH * NH * S_LEN * DK];
__device__ float g_v[BATCH * NH * S_LEN * DK];
__device__ float g_att[BATCH * S_LEN * HID];       // [b][s][hid]

__device__ __forceinline__ uint32_t f2tf32(float f) {
    uint32_t r;
    asm("cvt.rna.tf32.f32 %0, %1;" : "=r"(r) : "f"(f));
    return r;
}
__device__ __forceinline__ float tf32f(float f) {
    return __uint_as_float(f2tf32(f));
}

__device__ __forceinline__ void mma_tf32(float c[4], const uint32_t a[4],
                                         const uint32_t b[2]) {
    asm volatile(
        "mma.sync.aligned.m16n8k8.row.col.f32.tf32.tf32.f32 "
        "{%0,%1,%2,%3}, {%4,%5,%6,%7}, {%8,%9}, {%0,%1,%2,%3};"
        : "+f"(c[0]), "+f"(c[1]), "+f"(c[2]), "+f"(c[3])
        : "r"(a[0]), "r"(a[1]), "r"(a[2]), "r"(a[3]),
          "r"(b[0]), "r"(b[1]));
}

// Fast exp on the FMA pipe (avoids MUFU throughput wall).
// exp(x) = 2^(x*log2e); n = round(z), f = z-n in [-0.5,0.5], 2^f poly deg-4.
// Rel err ~4e-5. Valid for x <= 0 (softmax use); clamps hard-negatives to ~0.
__device__ __forceinline__ float fexp(float x) {
    float z = x * 1.44269504f;
    z = fmaxf(z, -125.0f);
    const float C = 12582912.0f;            // 1.5 * 2^23
    float nf = z + C;
    int n = __float_as_int(nf) - 0x4B400000;
    float f = z - (nf - C);
    float p = 0.00961813f;
    p = fmaf(p, f, 0.0555041f);
    p = fmaf(p, f, 0.240227f);
    p = fmaf(p, f, 0.693147f);
    p = fmaf(p, f, 1.0f);
    return __int_as_float(__float_as_int(p) + (n << 23));
}

// ---------------------------------------------------------------------------
// TF32 mma.sync GEMM-NT: out[m][n] = sum_k A[m][k] * W[n][k] + bias[n]
// (unchanged from R3 — 128x128 tile, BK=32, 8 warps, double-buffered)
// ---------------------------------------------------------------------------
#define PAD   36
#define TILEF (128 * PAD)
#define GEMM_SMEM_BYTES (4 * TILEF * 4)

__global__ __launch_bounds__(256) void gemm_mma(
    const float* __restrict__ A, const float* __restrict__ W,
    const float* __restrict__ bias, float* __restrict__ out, int qkv)
{
    extern __shared__ float sm[];
    float* sA[2] = { sm,             sm + 2 * TILEF };
    float* sW[2] = { sm + TILEF,     sm + 3 * TILEF };

    const int tid = threadIdx.x;
    const int wid = tid >> 5, lid = tid & 31;
    const int bn = blockIdx.x * 128;
    const int bm = blockIdx.y * 128;

    const int wm = wid >> 1;
    const int wn = wid & 1;
    const int g  = lid >> 2;
    const int tg = lid & 3;

    float c[2][8][4];
#pragma unroll
    for (int mi = 0; mi < 2; ++mi)
#pragma unroll
        for (int ni = 0; ni < 8; ++ni)
#pragma unroll
            for (int k = 0; k < 4; ++k) c[mi][ni][k] = 0.0f;

    float4 ra[4], rw[4];
#define LOAD_REGS(kk)                                                         \
    do {                                                                      \
        _Pragma("unroll")                                                     \
        for (int t = 0; t < 4; ++t) {                                         \
            const int idx = tid + t * 256;                                    \
            const int row = idx >> 3, c4 = idx & 7;                           \
            ra[t] = *(const float4*)(A + (size_t)(bm + row) * 1024 + (kk) + c4 * 4); \
            rw[t] = *(const float4*)(W + (size_t)(bn + row) * 1024 + (kk) + c4 * 4); \
        }                                                                     \
    } while (0)

#define STORE_SMEM(buf)                                                       \
    do {                                                                      \
        _Pragma("unroll")                                                     \
        for (int t = 0; t < 4; ++t) {                                         \
            const int idx = tid + t * 256;                                    \
            const int row = idx >> 3, c4 = idx & 7;                           \
            float* pa = sA[buf] + row * PAD + c4 * 4;                         \
            float* pw = sW[buf] + row * PAD + c4 * 4;                         \
            pa[0] = tf32f(ra[t].x); pa[1] = tf32f(ra[t].y);                   \
            pa[2] = tf32f(ra[t].z); pa[3] = tf32f(ra[t].w);                   \
            pw[0] = tf32f(rw[t].x); pw[1] = tf32f(rw[t].y);                   \
            pw[2] = tf32f(rw[t].z); pw[3] = tf32f(rw[t].w);                   \
        }                                                                     \
    } while (0)

    LOAD_REGS(0);
    STORE_SMEM(0);
    __syncthreads();

    for (int i = 0; i < 32; ++i) {
        const int cur = i & 1;
        if (i + 1 < 32) LOAD_REGS((i + 1) * 32);

        const float* As = sA[cur];
        const float* Ws = sW[cur];
#pragma unroll
        for (int ks = 0; ks < 4; ++ks) {
            const int kb = ks * 8;
            uint32_t af[2][4];
#pragma unroll
            for (int mi = 0; mi < 2; ++mi) {
                const int r0 = (wm * 32 + mi * 16 + g) * PAD + kb + tg;
                af[mi][0] = __float_as_uint(As[r0]);
                af[mi][1] = __float_as_uint(As[r0 + 8 * PAD]);
                af[mi][2] = __float_as_uint(As[r0 + 4]);
                af[mi][3] = __float_as_uint(As[r0 + 8 * PAD + 4]);
            }
            uint32_t bf[8][2];
#pragma unroll
            for (int ni = 0; ni < 8; ++ni) {
                const int r0 = (wn * 64 + ni * 8 + g) * PAD + kb + tg;
                bf[ni][0] = __float_as_uint(Ws[r0]);
                bf[ni][1] = __float_as_uint(Ws[r0 + 4]);
            }
#pragma unroll
            for (int mi = 0; mi < 2; ++mi)
#pragma unroll
                for (int ni = 0; ni < 8; ++ni)
                    mma_tf32(c[mi][ni], af[mi], bf[ni]);
        }

        if (i + 1 < 32) {
            __syncthreads();
            STORE_SMEM((i + 1) & 1);
            __syncthreads();
        }
    }

#pragma unroll
    for (int mi = 0; mi < 2; ++mi) {
        const int rowa = bm + wm * 32 + mi * 16 + g;
        const int rowb = rowa + 8;
#pragma unroll
        for (int ni = 0; ni < 8; ++ni) {
            const int col = bn + wn * 64 + ni * 8 + tg * 2;
            const float b0 = bias[col], b1 = bias[col + 1];
            float2 v0 = make_float2(c[mi][ni][0] + b0, c[mi][ni][1] + b1);
            float2 v1 = make_float2(c[mi][ni][2] + b0, c[mi][ni][3] + b1);
            if (qkv) {
                const int h = col >> 6, d = col & 63;
                const int ba = rowa >> 10, sa = rowa & 1023;
                const int bb = rowb >> 10, sb2 = rowb & 1023;
                *(float2*)(out + (((size_t)(ba * NH + h) * S_LEN + sa) * DK + d)) = v0;
                *(float2*)(out + (((size_t)(bb * NH + h) * S_LEN + sb2) * DK + d)) = v1;
            } else {
                *(float2*)(out + (size_t)rowa * HID + col) = v0;
                *(float2*)(out + (size_t)rowb * HID + col) = v1;
            }
        }
    }
}

// ---------------------------------------------------------------------------
// Tensor-core flash attention (tf32 mma.sync) with bias + zero-mask.
// CTA: 128 queries, 8 warps x 16 q-rows. K-tiles of 64.
// Smem (floats): Qs[128][68] | Ks[64][68] | Vs[64][68] | Ps[128][68]
// ---------------------------------------------------------------------------
#define APAD 68
#define QS_OFF 0
#define KS_OFF (128 * APAD)                 // 8704
#define VS_OFF (KS_OFF + 64 * APAD)         // 13056
#define PS_OFF (VS_OFF + 64 * APAD)         // 17408
#define ATTN_SMEM_BYTES ((PS_OFF + 128 * APAD) * 4)   // 104448

__global__ __launch_bounds__(256, 2) void attn_mma(
    const float* __restrict__ Qg, const float* __restrict__ Kg,
    const float* __restrict__ Vg, const float* __restrict__ Bias,
    float* __restrict__ O)
{
    extern __shared__ float sm[];
    float* Qs = sm + QS_OFF;
    float* Ks = sm + KS_OFF;
    float* Vs = sm + VS_OFF;
    float* Ps = sm + PS_OFF;

    const int q0 = blockIdx.x * 128;
    const int h  = blockIdx.y;
    const int b  = blockIdx.z;
    const int bh = b * NH + h;

    const float* qp = Qg + (size_t)bh * S_LEN * DK;
    const float* kp = Kg + (size_t)bh * S_LEN * DK;
    const float* vp = Vg + (size_t)bh * S_LEN * DK;
    const float* bp = Bias + (size_t)bh * S_LEN * S_LEN;

    const int tid = threadIdx.x;
    const int wid = tid >> 5, lid = tid & 31;
    const int g = lid >> 2, tg = lid & 3;
    const int qb = wid * 16;                 // warp's q-row base in tile

    // Load Q tile (scale + tf32): 2048 float4, 8 per thread
#pragma unroll
    for (int t = 0; t < 8; ++t) {
        const int idx = tid + t * 256;
        const int row = idx >> 4;
        const int c4  = (idx & 15) * 4;
        float4 v = *(const float4*)(qp + (size_t)(q0 + row) * DK + c4);
        float* p = Qs + row * APAD + c4;
        p[0] = tf32f(v.x * QK_SCALE);
        p[1] = tf32f(v.y * QK_SCALE);
        p[2] = tf32f(v.z * QK_SCALE);
        p[3] = tf32f(v.w * QK_SCALE);
    }

    float m0 = -1e30f, m1 = -1e30f, l0 = 0.0f, l1 = 0.0f;
    float acc[8][4];
#pragma unroll
    for (int ni = 0; ni < 8; ++ni)
#pragma unroll
        for (int j = 0; j < 4; ++j) acc[ni][j] = 0.0f;

    const int qrow0 = q0 + qb + g;       // this thread's first q row (global)

    for (int kt = 0; kt < 16; ++kt) {
        __syncthreads();
        // Load K,V tiles (tf32): 1024 float4 each, 4 per thread
#pragma unroll
        for (int t = 0; t < 4; ++t) {
            const int idx = tid + t * 256;
            const int row = idx >> 4;
            const int c4  = (idx & 15) * 4;
            float4 k4 = *(const float4*)(kp + (size_t)(kt * 64 + row) * DK + c4);
            float4 v4 = *(const float4*)(vp + (size_t)(kt * 64 + row) * DK + c4);
            float* pk = Ks + row * APAD + c4;
            float* pv = Vs + row * APAD + c4;
            pk[0] = tf32f(k4.x); pk[1] = tf32f(k4.y);
            pk[2] = tf32f(k4.z); pk[3] = tf32f(k4.w);
            pv[0] = tf32f(v4.x); pv[1] = tf32f(v4.y);
            pv[2] = tf32f(v4.z); pv[3] = tf32f(v4.w);
        }
        __syncthreads();

        // S = Q @ K^T   (warp: 16 x 64)
        float s[8][4];
#pragma unroll
        for (int ni = 0; ni < 8; ++ni)
#pragma unroll
            for (int j = 0; j < 4; ++j) s[ni][j] = 0.0f;
#pragma unroll
        for (int kc = 0; kc < 64; kc += 8) {
            uint32_t a[4];
            const float* qa = Qs + (qb + g) * APAD + kc + tg;
            a[0] = __float_as_uint(qa[0]);
            a[1] = __float_as_uint(qa[8 * APAD]);
            a[2] = __float_as_uint(qa[4]);
            a[3] = __float_as_uint(qa[8 * APAD + 4]);
#pragma unroll
            for (int ni = 0; ni < 8; ++ni) {
                uint32_t bb[2];
                const float* kb2 = Ks + (ni * 8 + g) * APAD + kc + tg;
                bb[0] = __float_as_uint(kb2[0]);
                bb[1] = __float_as_uint(kb2[4]);
                mma_tf32(s[ni], a, bb);
            }
        }

        // mask + bias (in place), row maxima
        float rm0 = -1e30f, rm1 = -1e30f;
#pragma unroll
        for (int ni = 0; ni < 8; ++ni) {
            const size_t boff = (size_t)qrow0 * S_LEN + kt * 64 + ni * 8 + tg * 2;
            float2 b0 = *(const float2*)(bp + boff);
            float2 b1 = *(const float2*)(bp + boff + 8 * S_LEN);
            s[ni][0] = (s[ni][0] == 0.0f ? NEGV : s[ni][0]) + b0.x;
            s[ni][1] = (s[ni][1] == 0.0f ? NEGV : s[ni][1]) + b0.y;
            s[ni][2] = (s[ni][2] == 0.0f ? NEGV : s[ni][2]) + b1.x;
            s[ni][3] = (s[ni][3] == 0.0f ? NEGV : s[ni][3]) + b1.y;
            rm0 = fmaxf(rm0, fmaxf(s[ni][0], s[ni][1]));
            rm1 = fmaxf(rm1, fmaxf(s[ni][2], s[ni][3]));
        }
        rm0 = fmaxf(rm0, __shfl_xor_sync(0xffffffffu, rm0, 1));
        rm0 = fmaxf(rm0, __shfl_xor_sync(0xffffffffu, rm0, 2));
        rm1 = fmaxf(rm1, __shfl_xor_sync(0xffffffffu, rm1, 1));
        rm1 = fmaxf(rm1, __shfl_xor_sync(0xffffffffu, rm1, 2));

        const float mn0 = fmaxf(m0, rm0);
        const float mn1 = fmaxf(m1, rm1);
        const float c0 = fexp(m0 - mn0);
        const float c1 = fexp(m1 - mn1);

        float ps0 = 0.0f, ps1 = 0.0f;
#pragma unroll
        for (int ni = 0; ni < 8; ++ni) {
            const float p00 = fexp(s[ni][0] - mn0);
            const float p01 = fexp(s[ni][1] - mn0);
            const float p10 = fexp(s[ni][2] - mn1);
            const float p11 = fexp(s[ni][3] - mn1);
            ps0 += p00 + p01;
            ps1 += p10 + p11;
            float* pr0 = Ps + (qb + g) * APAD + ni * 8 + tg * 2;
            pr0[0] = tf32f(p00); pr0[1] = tf32f(p01);
            float* pr1 = pr0 + 8 * APAD;
            pr1[0] = tf32f(p10); pr1[1] = tf32f(p11);
        }
        ps0 += __shfl_xor_sync(0xffffffffu, ps0, 1);
        ps0 += __shfl_xor_sync(0xffffffffu, ps0, 2);
        ps1 += __shfl_xor_sync(0xffffffffu, ps1, 1);
        ps1 += __shfl_xor_sync(0xffffffffu, ps1, 2);

        l0 = l0 * c0 + ps0;
        l1 = l1 * c1 + ps1;
        m0 = mn0;
        m1 = mn1;
#pragma unroll
        for (int ni = 0; ni < 8; ++ni) {
            acc[ni][0] *= c0; acc[ni][1] *= c0;
            acc[ni][2] *= c1; acc[ni][3] *= c1;
        }
        __syncwarp();

        // acc += P @ V   (warp: 16 x 64 over 64 keys)
#pragma unroll
        for (int kc = 0; kc < 64; kc += 8) {
            uint32_t a[4];
            const float* pa = Ps + (qb + g) * APAD + kc + tg;
            a[0] = __float_as_uint(pa[0]);
            a[1] = __float_as_uint(pa[8 * APAD]);
            a[2] = __float_as_uint(pa[4]);
            a[3] = __float_as_uint(pa[8 * APAD + 4]);
#pragma unroll
            for (int ni = 0; ni < 8; ++ni) {
                uint32_t bb[2];
                const float* vb = Vs + (kc + tg) * APAD + ni * 8 + g;
                bb[0] = __float_as_uint(vb[0]);
                bb[1] = __float_as_uint(vb[4 * APAD]);
                mma_tf32(acc[ni], a, bb);
            }
        }
        __syncwarp();   // Ps reads done before next tile's writes
    }

    // Epilogue: normalize and store to [b][s][hid]
    const float inv0 = 1.0f / l0;
    const float inv1 = 1.0f / l1;
#pragma unroll
    for (int ni = 0; ni < 8; ++ni) {
        const int col = h * DK + ni * 8 + tg * 2;
        float* o0 = O + (size_t)(b * S_LEN + qrow0) * HID + col;
        float* o1 = O + (size_t)(b * S_LEN + qrow0 + 8) * HID + col;
        *(float2*)o0 = make_float2(acc[ni][0] * inv0, acc[ni][1] * inv0);
        *(float2*)o1 = make_float2(acc[ni][2] * inv1, acc[ni][3] * inv1);
    }
}

// ---------------------------------------------------------------------------
extern "C" void kernel_launch(void* const* d_in, const int* in_sizes, int n_in,
                              void* d_out, int out_size)
{
    const float* batch = (const float*)d_in[0];
    const float* bias  = (const float*)d_in[1];
    const float* Wq = (const float*)d_in[2];
    const float* bq = (const float*)d_in[3];
    const float* Wk = (const float*)d_in[4];
    const float* bk = (const float*)d_in[5];
    const float* Wv = (const float*)d_in[6];
    const float* bv = (const float*)d_in[7];
    const float* Wo = (const float*)d_in[8];
    const float* bo = (const float*)d_in[9];
    float* out = (float*)d_out;

    float *qptr, *kptr, *vptr, *aptr;
    cudaGetSymbolAddress((void**)&qptr, g_q);
    cudaGetSymbolAddress((void**)&kptr, g_k);
    cudaGetSymbolAddress((void**)&vptr, g_v);
    cudaGetSymbolAddress((void**)&aptr, g_att);

    static int attr_set = 0;
    if (!attr_set) {
        cudaFuncSetAttribute(gemm_mma,
                             cudaFuncAttributeMaxDynamicSharedMemorySize,
                             GEMM_SMEM_BYTES);
        cudaFuncSetAttribute(attn_mma,
                             cudaFuncAttributeMaxDynamicSharedMemorySize,
                             ATTN_SMEM_BYTES);
        attr_set = 1;
    }

    dim3 ggrid(HID / 128, M_TOT / 128);   // (8, 32)
    gemm_mma<<<ggrid, 256, GEMM_SMEM_BYTES>>>(batch, Wq, bq, qptr, 1);
    gemm_mma<<<ggrid, 256, GEMM_SMEM_BYTES>>>(batch, Wk, bk, kptr, 1);
    gemm_mma<<<ggrid, 256, GEMM_SMEM_BYTES>>>(batch, Wv, bv, vptr, 1);

    dim3 agrid(S_LEN / 128, NH, BATCH);   // (8, 16, 4)
    attn_mma<<<agrid, 256, ATTN_SMEM_BYTES>>>(qptr, kptr, vptr, bias, aptr);

    gemm_mma<<<ggrid, 256, GEMM_SMEM_BYTES>>>(aptr, Wo, bo, out, 0);
}